// round 13
// baseline (speedup 1.0000x reference)
#include <cuda_runtime.h>
#include <cuda_bf16.h>

// ---------------------------------------------------------------------------
// Problem constants
// ---------------------------------------------------------------------------
#define NMAX   20000
#define EMAX   320000
#define HEADS  8
#define CH     64
#define HC     512
#define INCH   512
#define NB_SCAN ((NMAX + 255) / 256)

// ---------------------------------------------------------------------------
// Scratch (static device globals; no allocations allowed)
// ---------------------------------------------------------------------------
__device__ float    g_XLR[(size_t)NMAX * 1024]; // [:,0:512]=x@Wl, [:,512:1024]=x@Wr
__device__ unsigned g_XLB[(size_t)NMAX * 256];  // bf16x2 shadow of x@Wl (512 ch)
__device__ int      g_DEG[NMAX];
__device__ int      g_START[NMAX];
__device__ int      g_CURSOR[NMAX];
__device__ int      g_CSRC[EMAX];               // CSR source-node list
__device__ int      g_PART[NB_SCAN];
__device__ float    g_OUT[(size_t)NMAX * HC];
__device__ unsigned g_Z[(size_t)NMAX * (HC / 2)]; // bf16x2 relu(bn(out))
__device__ float    g_SUM[HC];
__device__ float    g_SSQ[HC];
__device__ float    g_CA[HC];
__device__ float    g_CB[HC];

// ---------------------------------------------------------------------------
// init: zero degree histogram + BN accumulators
// ---------------------------------------------------------------------------
__global__ void k_zero(int N)
{
    int i = blockIdx.x * blockDim.x + threadIdx.x;
    if (i < N) g_DEG[i] = 0;
    if (i < HC) { g_SUM[i] = 0.f; g_SSQ[i] = 0.f; }
}

// ---------------------------------------------------------------------------
// bf16 helpers
// ---------------------------------------------------------------------------
__device__ __forceinline__ unsigned pack_bf16(float lo, float hi)
{
    unsigned r;
    asm("cvt.rn.bf16x2.f32 %0, %1, %2;" : "=r"(r) : "f"(hi), "f"(lo));
    return r;
}

__device__ __forceinline__ void mma_bf16(float c[4], const unsigned a[4],
                                         const unsigned b[2])
{
    asm volatile(
        "mma.sync.aligned.m16n8k16.row.col.f32.bf16.bf16.f32 "
        "{%0,%1,%2,%3},{%4,%5,%6,%7},{%8,%9},{%0,%1,%2,%3};"
        : "+f"(c[0]), "+f"(c[1]), "+f"(c[2]), "+f"(c[3])
        : "r"(a[0]), "r"(a[1]), "r"(a[2]), "r"(a[3]),
          "r"(b[0]), "r"(b[1]));
}

// ---------------------------------------------------------------------------
// bf16 GEMM, double-buffered: g_XLR[M,1024] = x[M,512] @ [Wl | Wr]
// Also writes a packed-bf16 shadow of the Wl half into g_XLB.
// ---------------------------------------------------------------------------
#define KKPAD 132
__global__ __launch_bounds__(256) void k_gemm(const float* __restrict__ x,
                                              const float* __restrict__ Wl,
                                              const float* __restrict__ Wr,
                                              int M)
{
    __shared__ unsigned As2[2][8][KKPAD];
    __shared__ unsigned Bs2[2][8][KKPAD];

    const int bn   = blockIdx.x;
    const int row0 = blockIdx.y * 128;
    const float* W = (bn < 4) ? Wl : Wr;
    const int col0 = (bn & 3) * 128;

    const int tid  = threadIdx.x;
    const int warp = tid >> 5;
    const int lane = tid & 31;
    const int wm   = warp >> 1;
    const int wn   = warp & 1;
    const int gid  = lane >> 2;
    const int tig  = lane & 3;

    const int a_r = tid >> 2;
    const int a_c = (tid & 3) << 2;
    const int b_kk = tid >> 5;
    const int b_n  = (tid & 31) << 2;

    float c[2][8][4];
#pragma unroll
    for (int i = 0; i < 2; i++)
#pragma unroll
        for (int j = 0; j < 8; j++)
#pragma unroll
            for (int q = 0; q < 4; q++) c[i][j][q] = 0.f;

    float4 va[2];
    float4 vb0, vb1;

#pragma unroll
    for (int i = 0; i < 2; i++) {
        int gr = row0 + a_r + i * 64;
        va[i] = make_float4(0.f, 0.f, 0.f, 0.f);
        if (gr < M) va[i] = *(const float4*)(x + (size_t)gr * INCH + a_c);
    }
    vb0 = *(const float4*)(W + (size_t)(2 * b_kk) * HC + col0 + b_n);
    vb1 = *(const float4*)(W + (size_t)(2 * b_kk + 1) * HC + col0 + b_n);

#pragma unroll
    for (int i = 0; i < 2; i++) {
        int r = a_r + i * 64;
        As2[0][(a_c >> 1) + 0][r] = pack_bf16(va[i].x, va[i].y);
        As2[0][(a_c >> 1) + 1][r] = pack_bf16(va[i].z, va[i].w);
    }
    {
        uint4 t;
        t.x = pack_bf16(vb0.x, vb1.x);
        t.y = pack_bf16(vb0.y, vb1.y);
        t.z = pack_bf16(vb0.z, vb1.z);
        t.w = pack_bf16(vb0.w, vb1.w);
        *(uint4*)&Bs2[0][b_kk][b_n] = t;
    }
    __syncthreads();

    int buf = 0;
    for (int k0 = 0; k0 < INCH; k0 += 16) {
        const bool last = (k0 + 16 >= INCH);
        if (!last) {
#pragma unroll
            for (int i = 0; i < 2; i++) {
                int gr = row0 + a_r + i * 64;
                va[i] = make_float4(0.f, 0.f, 0.f, 0.f);
                if (gr < M)
                    va[i] = *(const float4*)(x + (size_t)gr * INCH + k0 + 16 + a_c);
            }
            vb0 = *(const float4*)(W + (size_t)(k0 + 16 + 2 * b_kk) * HC + col0 + b_n);
            vb1 = *(const float4*)(W + (size_t)(k0 + 16 + 2 * b_kk + 1) * HC + col0 + b_n);
        }

        {
            unsigned a[2][4];
#pragma unroll
            for (int mt = 0; mt < 2; mt++) {
                int mr = wm * 32 + mt * 16 + gid;
                a[mt][0] = As2[buf][tig][mr];
                a[mt][1] = As2[buf][tig][mr + 8];
                a[mt][2] = As2[buf][tig + 4][mr];
                a[mt][3] = As2[buf][tig + 4][mr + 8];
            }
            unsigned b[8][2];
#pragma unroll
            for (int nt = 0; nt < 8; nt++) {
                int nc = wn * 64 + nt * 8 + gid;
                b[nt][0] = Bs2[buf][tig][nc];
                b[nt][1] = Bs2[buf][tig + 4][nc];
            }
#pragma unroll
            for (int mt = 0; mt < 2; mt++)
#pragma unroll
                for (int nt = 0; nt < 8; nt++)
                    mma_bf16(c[mt][nt], a[mt], b[nt]);
        }

        if (!last) {
            int nb = buf ^ 1;
#pragma unroll
            for (int i = 0; i < 2; i++) {
                int r = a_r + i * 64;
                As2[nb][(a_c >> 1) + 0][r] = pack_bf16(va[i].x, va[i].y);
                As2[nb][(a_c >> 1) + 1][r] = pack_bf16(va[i].z, va[i].w);
            }
            uint4 t;
            t.x = pack_bf16(vb0.x, vb1.x);
            t.y = pack_bf16(vb0.y, vb1.y);
            t.z = pack_bf16(vb0.z, vb1.z);
            t.w = pack_bf16(vb0.w, vb1.w);
            *(uint4*)&Bs2[nb][b_kk][b_n] = t;
            __syncthreads();
            buf = nb;
        }
    }

    const bool isWl = (bn < 4);
#pragma unroll
    for (int mt = 0; mt < 2; mt++) {
#pragma unroll
        for (int nt = 0; nt < 8; nt++) {
            int r   = row0 + wm * 32 + mt * 16 + gid;
            int col = bn * 128 + wn * 64 + nt * 8 + 2 * tig;
            if (r < M) {
                *(float2*)(g_XLR + (size_t)r * 1024 + col) =
                    make_float2(c[mt][nt][0], c[mt][nt][1]);
                if (isWl)
                    g_XLB[(size_t)r * 256 + (col >> 1)] =
                        pack_bf16(c[mt][nt][0], c[mt][nt][1]);
            }
            if (r + 8 < M) {
                *(float2*)(g_XLR + (size_t)(r + 8) * 1024 + col) =
                    make_float2(c[mt][nt][2], c[mt][nt][3]);
                if (isWl)
                    g_XLB[(size_t)(r + 8) * 256 + (col >> 1)] =
                        pack_bf16(c[mt][nt][2], c[mt][nt][3]);
            }
        }
    }
}

// ---------------------------------------------------------------------------
// CSR build: histogram -> parallel scan -> scatter
// ---------------------------------------------------------------------------
__global__ void k_hist(const int* __restrict__ dst, int E)
{
    int e = blockIdx.x * blockDim.x + threadIdx.x;
    if (e < E) atomicAdd(&g_DEG[dst[e]], 1);
}

__global__ __launch_bounds__(256) void k_scan_part(int N)
{
    __shared__ int wsum[8];
    int i = blockIdx.x * 256 + threadIdx.x;
    int v = (i < N) ? g_DEG[i] : 0;
    int lane = threadIdx.x & 31, wid = threadIdx.x >> 5;
#pragma unroll
    for (int o = 16; o; o >>= 1) v += __shfl_xor_sync(0xffffffffu, v, o);
    if (lane == 0) wsum[wid] = v;
    __syncthreads();
    if (threadIdx.x == 0) {
        int s = 0;
#pragma unroll
        for (int w2 = 0; w2 < 8; w2++) s += wsum[w2];
        g_PART[blockIdx.x] = s;
    }
}

__global__ __launch_bounds__(256) void k_scan_final(int N, int nb)
{
    __shared__ int wsum[8];
    __shared__ int wscan[8];
    __shared__ int sh_base;
    const int b = blockIdx.x;
    const int t = threadIdx.x;
    const int lane = t & 31, wid = t >> 5;

    int ps = 0;
    for (int i = t; i < b; i += 256) ps += g_PART[i];
#pragma unroll
    for (int o = 16; o; o >>= 1) ps += __shfl_xor_sync(0xffffffffu, ps, o);
    if (lane == 0) wsum[wid] = ps;
    __syncthreads();
    if (t == 0) {
        int s = 0;
#pragma unroll
        for (int w2 = 0; w2 < 8; w2++) s += wsum[w2];
        sh_base = s;
    }
    __syncthreads();
    const int base = sh_base;

    int i = b * 256 + t;
    int v = (i < N) ? g_DEG[i] : 0;
    int xinc = v;
#pragma unroll
    for (int o = 1; o < 32; o <<= 1) {
        int y = __shfl_up_sync(0xffffffffu, xinc, o);
        if (lane >= o) xinc += y;
    }
    if (lane == 31) wscan[wid] = xinc;
    __syncthreads();
    int off = 0;
#pragma unroll
    for (int w2 = 0; w2 < 8; w2++) off += (w2 < wid) ? wscan[w2] : 0;
    if (i < N) {
        int e = base + off + xinc - v;
        g_START[i]  = e;
        g_CURSOR[i] = e;
    }
}

__global__ void k_scatter(const int* __restrict__ src,
                          const int* __restrict__ dst, int E)
{
    int e = blockIdx.x * blockDim.x + threadIdx.x;
    if (e >= E) return;
    int d   = dst[e];
    int pos = atomicAdd(&g_CURSOR[d], 1);
    g_CSRC[pos] = src[e];
}

// ---------------------------------------------------------------------------
// Fused GATv2 with ONLINE softmax, bf16 gather payload, 2 edges per iter.
// One warp per destination node. Lane owns channels c = lane*4 + 128*k,
// i.e. bf16x2 words lane*2 + 64*k (uint2 per chunk).
// After the 16-lane butterfly, lane holds the logit of head 2k+(lane>>4).
// ---------------------------------------------------------------------------
__global__ __launch_bounds__(256) void k_edge(const float* __restrict__ att, int N)
{
    int w    = (blockIdx.x * blockDim.x + threadIdx.x) >> 5;
    int lane = threadIdx.x & 31;
    if (w >= N) return;
    const int d     = w;
    const int start = g_START[d];
    const int deg   = g_DEG[d];
    const int c0    = lane * 4;
    const int w0    = lane * 2;          // bf16x2 word offset within chunk

    float4 attv[4], xrv[4];
#pragma unroll
    for (int k = 0; k < 4; k++) {
        attv[k] = __ldg((const float4*)(att + c0 + 128 * k));
        xrv[k]  = *(const float4*)(g_XLR + (size_t)d * 1024 + 512 + c0 + 128 * k);
    }

    float  m[4], dnm[4];
    float4 acc[4];
#pragma unroll
    for (int k = 0; k < 4; k++) {
        m[k] = -1e30f; dnm[k] = 0.f;
        acc[k] = make_float4(0.f, 0.f, 0.f, 0.f);
    }

    int j = 0;
    for (; j + 2 <= deg; j += 2) {
        int s0 = g_CSRC[start + j];
        int s1 = g_CSRC[start + j + 1];
        const unsigned* xb0 = g_XLB + (size_t)s0 * 256;
        const unsigned* xb1 = g_XLB + (size_t)s1 * 256;
        uint2 raw[2][4];
#pragma unroll
        for (int k = 0; k < 4; k++) raw[0][k] = *(const uint2*)(xb0 + w0 + 64 * k);
#pragma unroll
        for (int k = 0; k < 4; k++) raw[1][k] = *(const uint2*)(xb1 + w0 + 64 * k);

#pragma unroll
        for (int e2 = 0; e2 < 2; e2++) {
            float4 v[4];
            float  p[4];
#pragma unroll
            for (int k = 0; k < 4; k++) {
                float2 lo = __bfloat1622float2(*(const __nv_bfloat162*)&raw[e2][k].x);
                float2 hi = __bfloat1622float2(*(const __nv_bfloat162*)&raw[e2][k].y);
                v[k] = make_float4(lo.x, lo.y, hi.x, hi.y);
                float tx = v[k].x + xrv[k].x, ty = v[k].y + xrv[k].y;
                float tz = v[k].z + xrv[k].z, tw = v[k].w + xrv[k].w;
                tx = (tx > 0.f) ? tx : 0.2f * tx;
                ty = (ty > 0.f) ? ty : 0.2f * ty;
                tz = (tz > 0.f) ? tz : 0.2f * tz;
                tw = (tw > 0.f) ? tw : 0.2f * tw;
                p[k] = tx * attv[k].x + ty * attv[k].y +
                       tz * attv[k].z + tw * attv[k].w;
            }
#pragma unroll
            for (int k = 0; k < 4; k++) {
                p[k] += __shfl_xor_sync(0xffffffffu, p[k], 1);
                p[k] += __shfl_xor_sync(0xffffffffu, p[k], 2);
                p[k] += __shfl_xor_sync(0xffffffffu, p[k], 4);
                p[k] += __shfl_xor_sync(0xffffffffu, p[k], 8);
            }
#pragma unroll
            for (int k = 0; k < 4; k++) {
                float mn = fmaxf(m[k], p[k]);
                float r  = __expf(m[k] - mn);
                float e  = __expf(p[k] - mn);
                dnm[k]   = fmaf(dnm[k], r, e);
                acc[k].x = fmaf(acc[k].x, r, e * v[k].x);
                acc[k].y = fmaf(acc[k].y, r, e * v[k].y);
                acc[k].z = fmaf(acc[k].z, r, e * v[k].z);
                acc[k].w = fmaf(acc[k].w, r, e * v[k].w);
                m[k] = mn;
            }
        }
    }
    if (j < deg) {
        int s = g_CSRC[start + j];
        const unsigned* xb = g_XLB + (size_t)s * 256;
        float4 v[4];
        float  p[4];
#pragma unroll
        for (int k = 0; k < 4; k++) {
            uint2 raw = *(const uint2*)(xb + w0 + 64 * k);
            float2 lo = __bfloat1622float2(*(const __nv_bfloat162*)&raw.x);
            float2 hi = __bfloat1622float2(*(const __nv_bfloat162*)&raw.y);
            v[k] = make_float4(lo.x, lo.y, hi.x, hi.y);
            float tx = v[k].x + xrv[k].x, ty = v[k].y + xrv[k].y;
            float tz = v[k].z + xrv[k].z, tw = v[k].w + xrv[k].w;
            tx = (tx > 0.f) ? tx : 0.2f * tx;
            ty = (ty > 0.f) ? ty : 0.2f * ty;
            tz = (tz > 0.f) ? tz : 0.2f * tz;
            tw = (tw > 0.f) ? tw : 0.2f * tw;
            p[k] = tx * attv[k].x + ty * attv[k].y + tz * attv[k].z + tw * attv[k].w;
        }
#pragma unroll
        for (int k = 0; k < 4; k++) {
            p[k] += __shfl_xor_sync(0xffffffffu, p[k], 1);
            p[k] += __shfl_xor_sync(0xffffffffu, p[k], 2);
            p[k] += __shfl_xor_sync(0xffffffffu, p[k], 4);
            p[k] += __shfl_xor_sync(0xffffffffu, p[k], 8);
        }
#pragma unroll
        for (int k = 0; k < 4; k++) {
            float mn = fmaxf(m[k], p[k]);
            float r  = __expf(m[k] - mn);
            float e  = __expf(p[k] - mn);
            dnm[k]   = fmaf(dnm[k], r, e);
            acc[k].x = fmaf(acc[k].x, r, e * v[k].x);
            acc[k].y = fmaf(acc[k].y, r, e * v[k].y);
            acc[k].z = fmaf(acc[k].z, r, e * v[k].z);
            acc[k].w = fmaf(acc[k].w, r, e * v[k].w);
            m[k] = mn;
        }
    }

#pragma unroll
    for (int k = 0; k < 4; k++) {
        float inv = 1.0f / (dnm[k] + 1e-16f);
        float4 o = make_float4(acc[k].x * inv, acc[k].y * inv,
                               acc[k].z * inv, acc[k].w * inv);
        *(float4*)(g_OUT + (size_t)d * HC + c0 + 128 * k) = o;
    }
}

// ---------------------------------------------------------------------------
// BatchNorm stats (4-row unroll) / coefficients
// ---------------------------------------------------------------------------
__global__ __launch_bounds__(512) void k_bn_stats(int n_nodes, int rows_per)
{
    int j  = threadIdx.x;
    int r0 = blockIdx.x * rows_per;
    int r1 = min(r0 + rows_per, n_nodes);
    float s = 0.f, q = 0.f;
    int r = r0;
    for (; r + 4 <= r1; r += 4) {
        float v0 = g_OUT[(size_t)(r + 0) * HC + j];
        float v1 = g_OUT[(size_t)(r + 1) * HC + j];
        float v2 = g_OUT[(size_t)(r + 2) * HC + j];
        float v3 = g_OUT[(size_t)(r + 3) * HC + j];
        s += v0 + v1 + v2 + v3;
        q = fmaf(v0, v0, q);
        q = fmaf(v1, v1, q);
        q = fmaf(v2, v2, q);
        q = fmaf(v3, v3, q);
    }
    for (; r < r1; r++) {
        float v = g_OUT[(size_t)r * HC + j];
        s += v;
        q = fmaf(v, v, q);
    }
    atomicAdd(&g_SUM[j], s);
    atomicAdd(&g_SSQ[j], q);
}

__global__ void k_bn_coef(const float* __restrict__ gamma,
                          const float* __restrict__ beta, float invN)
{
    int j = threadIdx.x;
    float mu  = g_SUM[j] * invN;
    float var = g_SSQ[j] * invN - mu * mu;
    float a   = gamma[j] * rsqrtf(var + 1e-5f);
    g_CA[j] = a;
    g_CB[j] = beta[j] - mu * a;
}

// ---------------------------------------------------------------------------
// z = bf16(relu(bn(out))) materialization
// ---------------------------------------------------------------------------
__global__ __launch_bounds__(256) void k_z(int N)
{
    int i = blockIdx.x * blockDim.x + threadIdx.x;
    if (i >= N * (HC / 2)) return;
    int wd = i & (HC / 2 - 1);
    float2 v  = *(const float2*)(g_OUT + (size_t)i * 2);
    float2 ca = *(const float2*)(g_CA + wd * 2);
    float2 cb = *(const float2*)(g_CB + wd * 2);
    float lo = fmaxf(fmaf(v.x, ca.x, cb.x), 0.f);
    float hi = fmaxf(fmaf(v.y, ca.y, cb.y), 0.f);
    g_Z[i] = pack_bf16(lo, hi);
}

// ---------------------------------------------------------------------------
// Link scoring from bf16 z: 2 label-edges per warp, uint4 gathers
// ---------------------------------------------------------------------------
__global__ __launch_bounds__(256) void k_score(const int* __restrict__ li,
                                               int EL, float* __restrict__ out)
{
    int w    = (blockIdx.x * blockDim.x + threadIdx.x) >> 5;
    int lane = threadIdx.x & 31;
    int e0 = w * 2;
    if (e0 >= EL) return;
    int ne = (e0 + 1 < EL) ? 2 : 1;

    float accv[2] = {0.f, 0.f};
#pragma unroll
    for (int q = 0; q < 2; q++) {
        if (q >= ne) break;
        int s = li[e0 + q];
        int t = li[EL + e0 + q];
        const uint4* ps = (const uint4*)(g_Z + (size_t)s * (HC / 2));
        const uint4* pt = (const uint4*)(g_Z + (size_t)t * (HC / 2));
        float acc = 0.f;
#pragma unroll
        for (int k = 0; k < 2; k++) {
            uint4 a4 = ps[lane + 32 * k];
            uint4 b4 = pt[lane + 32 * k];
            const unsigned* au = &a4.x;
            const unsigned* bu = &b4.x;
#pragma unroll
            for (int r = 0; r < 4; r++) {
                float2 af = __bfloat1622float2(*(const __nv_bfloat162*)&au[r]);
                float2 bf = __bfloat1622float2(*(const __nv_bfloat162*)&bu[r]);
                acc = fmaf(af.x, bf.x, acc);
                acc = fmaf(af.y, bf.y, acc);
            }
        }
        accv[q] = acc;
    }
#pragma unroll
    for (int q = 0; q < 2; q++) {
#pragma unroll
        for (int o = 16; o; o >>= 1)
            accv[q] += __shfl_xor_sync(0xffffffffu, accv[q], o);
    }
    if (lane == 0) {
        out[e0] = accv[0];
        if (ne == 2) out[e0 + 1] = accv[1];
    }
}

// ---------------------------------------------------------------------------
// Launch
// ---------------------------------------------------------------------------
extern "C" void kernel_launch(void* const* d_in, const int* in_sizes, int n_in,
                              void* d_out, int out_size)
{
    const float* x     = (const float*)d_in[0];
    const int*   ei    = (const int*)d_in[1];
    const int*   eli   = (const int*)d_in[2];
    const float* Wl    = (const float*)d_in[3];
    const float* Wr    = (const float*)d_in[4];
    const float* att   = (const float*)d_in[5];
    // d_in[6] = bias: cancels under BatchNorm (mean-subtracted), unused
    const float* gamma = (const float*)d_in[7];
    const float* beta  = (const float*)d_in[8];
    float* out = (float*)d_out;

    const int N  = in_sizes[0] / INCH;
    const int E  = in_sizes[1] / 2;
    const int EL = in_sizes[2] / 2;
    const int* src = ei;
    const int* dst = ei + E;
    const int nb = (N + 255) / 256;

    k_zero<<<(N + 255) / 256, 256>>>(N);

    {
        dim3 grid(8, (N + 127) / 128);
        k_gemm<<<grid, 256>>>(x, Wl, Wr, N);
    }

    k_hist<<<(E + 255) / 256, 256>>>(dst, E);
    k_scan_part<<<nb, 256>>>(N);
    k_scan_final<<<nb, 256>>>(N, nb);
    k_scatter<<<(E + 255) / 256, 256>>>(src, dst, E);

    // one warp per node, bf16 payload, 2-edge unrolled
    k_edge<<<(N * 32 + 255) / 256, 256>>>(att, N);

    {
        int rows_per = 40;
        int blocks = (N + rows_per - 1) / rows_per;
        k_bn_stats<<<blocks, 512>>>(N, rows_per);
        k_bn_coef<<<1, HC>>>(gamma, beta, 1.0f / (float)N);
    }

    {
        int words = N * (HC / 2);
        k_z<<<(words + 255) / 256, 256>>>(N);
    }

    {
        int warps = (EL + 1) / 2;
        k_score<<<(warps * 32 + 255) / 256, 256>>>(eli, EL, out);
    }
}

// round 14
// speedup vs baseline: 1.0447x; 1.0447x over previous
#include <cuda_runtime.h>
#include <cuda_bf16.h>

// ---------------------------------------------------------------------------
// Problem constants
// ---------------------------------------------------------------------------
#define NMAX   20000
#define EMAX   320000
#define HEADS  8
#define CH     64
#define HC     512
#define INCH   512

// ---------------------------------------------------------------------------
// Scratch (static device globals; no allocations allowed)
// ---------------------------------------------------------------------------
__device__ float    g_XLR[(size_t)NMAX * 1024]; // [:,0:512]=x@Wl, [:,512:1024]=x@Wr
__device__ int      g_DEG[NMAX];
__device__ int      g_START[NMAX];
__device__ int      g_CURSOR[NMAX];
__device__ int      g_CSRC[EMAX];               // CSR source-node list
__device__ float    g_OUT[(size_t)NMAX * HC];
__device__ unsigned g_Z[(size_t)NMAX * (HC / 2)]; // bf16x2 relu(bn(out))
__device__ float    g_SUM[HC];
__device__ float    g_SSQ[HC];

// ---------------------------------------------------------------------------
// init: zero degree histogram + BN accumulators
// ---------------------------------------------------------------------------
__global__ void k_zero(int N)
{
    int i = blockIdx.x * blockDim.x + threadIdx.x;
    if (i < N) g_DEG[i] = 0;
    if (i < HC) { g_SUM[i] = 0.f; g_SSQ[i] = 0.f; }
}

// ---------------------------------------------------------------------------
// bf16 helpers
// ---------------------------------------------------------------------------
__device__ __forceinline__ unsigned pack_bf16(float lo, float hi)
{
    unsigned r;
    asm("cvt.rn.bf16x2.f32 %0, %1, %2;" : "=r"(r) : "f"(hi), "f"(lo));
    return r;
}

__device__ __forceinline__ void mma_bf16(float c[4], const unsigned a[4],
                                         const unsigned b[2])
{
    asm volatile(
        "mma.sync.aligned.m16n8k16.row.col.f32.bf16.bf16.f32 "
        "{%0,%1,%2,%3},{%4,%5,%6,%7},{%8,%9},{%0,%1,%2,%3};"
        : "+f"(c[0]), "+f"(c[1]), "+f"(c[2]), "+f"(c[3])
        : "r"(a[0]), "r"(a[1]), "r"(a[2]), "r"(a[3]),
          "r"(b[0]), "r"(b[1]));
}

// ---------------------------------------------------------------------------
// bf16 GEMM, double-buffered: g_XLR[M,1024] = x[M,512] @ [Wl | Wr]
// block tile 128x128, BK=16, 256 thr = 8 warps, warp tile 32x64.
// ---------------------------------------------------------------------------
#define KKPAD 132
__global__ __launch_bounds__(256) void k_gemm(const float* __restrict__ x,
                                              const float* __restrict__ Wl,
                                              const float* __restrict__ Wr,
                                              int M)
{
    __shared__ unsigned As2[2][8][KKPAD];
    __shared__ unsigned Bs2[2][8][KKPAD];

    const int bn   = blockIdx.x;
    const int row0 = blockIdx.y * 128;
    const float* W = (bn < 4) ? Wl : Wr;
    const int col0 = (bn & 3) * 128;

    const int tid  = threadIdx.x;
    const int warp = tid >> 5;
    const int lane = tid & 31;
    const int wm   = warp >> 1;
    const int wn   = warp & 1;
    const int gid  = lane >> 2;
    const int tig  = lane & 3;

    const int a_r = tid >> 2;
    const int a_c = (tid & 3) << 2;
    const int b_kk = tid >> 5;
    const int b_n  = (tid & 31) << 2;

    float c[2][8][4];
#pragma unroll
    for (int i = 0; i < 2; i++)
#pragma unroll
        for (int j = 0; j < 8; j++)
#pragma unroll
            for (int q = 0; q < 4; q++) c[i][j][q] = 0.f;

    float4 va[2];
    float4 vb0, vb1;

#pragma unroll
    for (int i = 0; i < 2; i++) {
        int gr = row0 + a_r + i * 64;
        va[i] = make_float4(0.f, 0.f, 0.f, 0.f);
        if (gr < M) va[i] = *(const float4*)(x + (size_t)gr * INCH + a_c);
    }
    vb0 = *(const float4*)(W + (size_t)(2 * b_kk) * HC + col0 + b_n);
    vb1 = *(const float4*)(W + (size_t)(2 * b_kk + 1) * HC + col0 + b_n);

#pragma unroll
    for (int i = 0; i < 2; i++) {
        int r = a_r + i * 64;
        As2[0][(a_c >> 1) + 0][r] = pack_bf16(va[i].x, va[i].y);
        As2[0][(a_c >> 1) + 1][r] = pack_bf16(va[i].z, va[i].w);
    }
    {
        uint4 t;
        t.x = pack_bf16(vb0.x, vb1.x);
        t.y = pack_bf16(vb0.y, vb1.y);
        t.z = pack_bf16(vb0.z, vb1.z);
        t.w = pack_bf16(vb0.w, vb1.w);
        *(uint4*)&Bs2[0][b_kk][b_n] = t;
    }
    __syncthreads();

    int buf = 0;
    for (int k0 = 0; k0 < INCH; k0 += 16) {
        const bool last = (k0 + 16 >= INCH);
        if (!last) {
#pragma unroll
            for (int i = 0; i < 2; i++) {
                int gr = row0 + a_r + i * 64;
                va[i] = make_float4(0.f, 0.f, 0.f, 0.f);
                if (gr < M)
                    va[i] = *(const float4*)(x + (size_t)gr * INCH + k0 + 16 + a_c);
            }
            vb0 = *(const float4*)(W + (size_t)(k0 + 16 + 2 * b_kk) * HC + col0 + b_n);
            vb1 = *(const float4*)(W + (size_t)(k0 + 16 + 2 * b_kk + 1) * HC + col0 + b_n);
        }

        {
            unsigned a[2][4];
#pragma unroll
            for (int mt = 0; mt < 2; mt++) {
                int mr = wm * 32 + mt * 16 + gid;
                a[mt][0] = As2[buf][tig][mr];
                a[mt][1] = As2[buf][tig][mr + 8];
                a[mt][2] = As2[buf][tig + 4][mr];
                a[mt][3] = As2[buf][tig + 4][mr + 8];
            }
            unsigned b[8][2];
#pragma unroll
            for (int nt = 0; nt < 8; nt++) {
                int nc = wn * 64 + nt * 8 + gid;
                b[nt][0] = Bs2[buf][tig][nc];
                b[nt][1] = Bs2[buf][tig + 4][nc];
            }
#pragma unroll
            for (int mt = 0; mt < 2; mt++)
#pragma unroll
                for (int nt = 0; nt < 8; nt++)
                    mma_bf16(c[mt][nt], a[mt], b[nt]);
        }

        if (!last) {
            int nb = buf ^ 1;
#pragma unroll
            for (int i = 0; i < 2; i++) {
                int r = a_r + i * 64;
                As2[nb][(a_c >> 1) + 0][r] = pack_bf16(va[i].x, va[i].y);
                As2[nb][(a_c >> 1) + 1][r] = pack_bf16(va[i].z, va[i].w);
            }
            uint4 t;
            t.x = pack_bf16(vb0.x, vb1.x);
            t.y = pack_bf16(vb0.y, vb1.y);
            t.z = pack_bf16(vb0.z, vb1.z);
            t.w = pack_bf16(vb0.w, vb1.w);
            *(uint4*)&Bs2[nb][b_kk][b_n] = t;
            __syncthreads();
            buf = nb;
        }
    }

#pragma unroll
    for (int mt = 0; mt < 2; mt++) {
#pragma unroll
        for (int nt = 0; nt < 8; nt++) {
            int r   = row0 + wm * 32 + mt * 16 + gid;
            int col = bn * 128 + wn * 64 + nt * 8 + 2 * tig;
            if (r < M)
                *(float2*)(g_XLR + (size_t)r * 1024 + col) =
                    make_float2(c[mt][nt][0], c[mt][nt][1]);
            if (r + 8 < M)
                *(float2*)(g_XLR + (size_t)(r + 8) * 1024 + col) =
                    make_float2(c[mt][nt][2], c[mt][nt][3]);
        }
    }
}

// ---------------------------------------------------------------------------
// CSR build: histogram -> single-kernel scan -> scatter
// ---------------------------------------------------------------------------
__global__ void k_hist(const int* __restrict__ dst, int E)
{
    int e = blockIdx.x * blockDim.x + threadIdx.x;
    if (e < E) atomicAdd(&g_DEG[dst[e]], 1);
}

// One kernel: each block strided-sums g_DEG[0, b*256) for its base, then
// does the local 256-element exclusive scan. Replaces the 2-kernel scan.
__global__ __launch_bounds__(256) void k_scan(int N)
{
    __shared__ int wsum[8];
    __shared__ int wscan[8];
    __shared__ int sh_base;
    const int b = blockIdx.x;
    const int t = threadIdx.x;
    const int lane = t & 31, wid = t >> 5;

    // base = sum of degrees before this block's region
    int ps = 0;
    int lim = b * 256;
    for (int i = t; i < lim; i += 256) ps += g_DEG[i];
#pragma unroll
    for (int o = 16; o; o >>= 1) ps += __shfl_xor_sync(0xffffffffu, ps, o);
    if (lane == 0) wsum[wid] = ps;
    __syncthreads();
    if (t == 0) {
        int s = 0;
#pragma unroll
        for (int w2 = 0; w2 < 8; w2++) s += wsum[w2];
        sh_base = s;
    }
    __syncthreads();
    const int base = sh_base;

    // local exclusive scan of this block's 256 degrees
    int i = b * 256 + t;
    int v = (i < N) ? g_DEG[i] : 0;
    int xinc = v;
#pragma unroll
    for (int o = 1; o < 32; o <<= 1) {
        int y = __shfl_up_sync(0xffffffffu, xinc, o);
        if (lane >= o) xinc += y;
    }
    if (lane == 31) wscan[wid] = xinc;
    __syncthreads();
    int off = 0;
#pragma unroll
    for (int w2 = 0; w2 < 8; w2++) off += (w2 < wid) ? wscan[w2] : 0;
    if (i < N) {
        int e = base + off + xinc - v;
        g_START[i]  = e;
        g_CURSOR[i] = e;
    }
}

__global__ void k_scatter(const int* __restrict__ src,
                          const int* __restrict__ dst, int E)
{
    int e = blockIdx.x * blockDim.x + threadIdx.x;
    if (e >= E) return;
    int d   = dst[e];
    int pos = atomicAdd(&g_CURSOR[d], 1);
    g_CSRC[pos] = src[e];
}

// ---------------------------------------------------------------------------
// Fused GATv2 with ONLINE softmax, 2 edges per iteration (empirical optimum:
// fp32 payload — bf16 gather regressed (latency-bound, cvt chain);
// 4-edge unroll spills; 2-warp split duplicates index traffic).
// One warp per destination node. Lane owns channels c = lane*4 + 128*k.
// After the 16-lane butterfly, lane holds the logit of head 2k+(lane>>4).
// ---------------------------------------------------------------------------
__global__ __launch_bounds__(256) void k_edge(const float* __restrict__ att, int N)
{
    int w    = (blockIdx.x * blockDim.x + threadIdx.x) >> 5;
    int lane = threadIdx.x & 31;
    if (w >= N) return;
    const int d     = w;
    const int start = g_START[d];
    const int deg   = g_DEG[d];
    const int c0    = lane * 4;

    float4 attv[4], xrv[4];
#pragma unroll
    for (int k = 0; k < 4; k++) {
        attv[k] = __ldg((const float4*)(att + c0 + 128 * k));
        xrv[k]  = *(const float4*)(g_XLR + (size_t)d * 1024 + 512 + c0 + 128 * k);
    }

    float  m[4], dnm[4];
    float4 acc[4];
#pragma unroll
    for (int k = 0; k < 4; k++) {
        m[k] = -1e30f; dnm[k] = 0.f;
        acc[k] = make_float4(0.f, 0.f, 0.f, 0.f);
    }

    int j = 0;
    for (; j + 2 <= deg; j += 2) {
        int s0 = g_CSRC[start + j];
        int s1 = g_CSRC[start + j + 1];
        const float* xl0 = g_XLR + (size_t)s0 * 1024;
        const float* xl1 = g_XLR + (size_t)s1 * 1024;
        float4 v[2][4];
        float  p[2][4];
#pragma unroll
        for (int k = 0; k < 4; k++) v[0][k] = *(const float4*)(xl0 + c0 + 128 * k);
#pragma unroll
        for (int k = 0; k < 4; k++) v[1][k] = *(const float4*)(xl1 + c0 + 128 * k);

#pragma unroll
        for (int e2 = 0; e2 < 2; e2++) {
#pragma unroll
            for (int k = 0; k < 4; k++) {
                float tx = v[e2][k].x + xrv[k].x, ty = v[e2][k].y + xrv[k].y;
                float tz = v[e2][k].z + xrv[k].z, tw = v[e2][k].w + xrv[k].w;
                tx = (tx > 0.f) ? tx : 0.2f * tx;
                ty = (ty > 0.f) ? ty : 0.2f * ty;
                tz = (tz > 0.f) ? tz : 0.2f * tz;
                tw = (tw > 0.f) ? tw : 0.2f * tw;
                p[e2][k] = tx * attv[k].x + ty * attv[k].y +
                           tz * attv[k].z + tw * attv[k].w;
            }
        }
#pragma unroll
        for (int e2 = 0; e2 < 2; e2++)
#pragma unroll
            for (int k = 0; k < 4; k++) {
                p[e2][k] += __shfl_xor_sync(0xffffffffu, p[e2][k], 1);
                p[e2][k] += __shfl_xor_sync(0xffffffffu, p[e2][k], 2);
                p[e2][k] += __shfl_xor_sync(0xffffffffu, p[e2][k], 4);
                p[e2][k] += __shfl_xor_sync(0xffffffffu, p[e2][k], 8);
            }
#pragma unroll
        for (int e2 = 0; e2 < 2; e2++) {
#pragma unroll
            for (int k = 0; k < 4; k++) {
                float mn = fmaxf(m[k], p[e2][k]);
                float r  = __expf(m[k] - mn);
                float e  = __expf(p[e2][k] - mn);
                dnm[k]   = fmaf(dnm[k], r, e);
                acc[k].x = fmaf(acc[k].x, r, e * v[e2][k].x);
                acc[k].y = fmaf(acc[k].y, r, e * v[e2][k].y);
                acc[k].z = fmaf(acc[k].z, r, e * v[e2][k].z);
                acc[k].w = fmaf(acc[k].w, r, e * v[e2][k].w);
                m[k] = mn;
            }
        }
    }
    if (j < deg) {
        int s = g_CSRC[start + j];
        const float* xl = g_XLR + (size_t)s * 1024;
        float4 v[4];
        float  p[4];
#pragma unroll
        for (int k = 0; k < 4; k++) {
            v[k] = *(const float4*)(xl + c0 + 128 * k);
            float tx = v[k].x + xrv[k].x, ty = v[k].y + xrv[k].y;
            float tz = v[k].z + xrv[k].z, tw = v[k].w + xrv[k].w;
            tx = (tx > 0.f) ? tx : 0.2f * tx;
            ty = (ty > 0.f) ? ty : 0.2f * ty;
            tz = (tz > 0.f) ? tz : 0.2f * tz;
            tw = (tw > 0.f) ? tw : 0.2f * tw;
            p[k] = tx * attv[k].x + ty * attv[k].y + tz * attv[k].z + tw * attv[k].w;
        }
#pragma unroll
        for (int k = 0; k < 4; k++) {
            p[k] += __shfl_xor_sync(0xffffffffu, p[k], 1);
            p[k] += __shfl_xor_sync(0xffffffffu, p[k], 2);
            p[k] += __shfl_xor_sync(0xffffffffu, p[k], 4);
            p[k] += __shfl_xor_sync(0xffffffffu, p[k], 8);
        }
#pragma unroll
        for (int k = 0; k < 4; k++) {
            float mn = fmaxf(m[k], p[k]);
            float r  = __expf(m[k] - mn);
            float e  = __expf(p[k] - mn);
            dnm[k]   = fmaf(dnm[k], r, e);
            acc[k].x = fmaf(acc[k].x, r, e * v[k].x);
            acc[k].y = fmaf(acc[k].y, r, e * v[k].y);
            acc[k].z = fmaf(acc[k].z, r, e * v[k].z);
            acc[k].w = fmaf(acc[k].w, r, e * v[k].w);
            m[k] = mn;
        }
    }

#pragma unroll
    for (int k = 0; k < 4; k++) {
        float inv = 1.0f / (dnm[k] + 1e-16f);
        float4 o = make_float4(acc[k].x * inv, acc[k].y * inv,
                               acc[k].z * inv, acc[k].w * inv);
        *(float4*)(g_OUT + (size_t)d * HC + c0 + 128 * k) = o;
    }
}

// ---------------------------------------------------------------------------
// BatchNorm stats (4-row unroll)
// ---------------------------------------------------------------------------
__global__ __launch_bounds__(512) void k_bn_stats(int n_nodes, int rows_per)
{
    int j  = threadIdx.x;
    int r0 = blockIdx.x * rows_per;
    int r1 = min(r0 + rows_per, n_nodes);
    float s = 0.f, q = 0.f;
    int r = r0;
    for (; r + 4 <= r1; r += 4) {
        float v0 = g_OUT[(size_t)(r + 0) * HC + j];
        float v1 = g_OUT[(size_t)(r + 1) * HC + j];
        float v2 = g_OUT[(size_t)(r + 2) * HC + j];
        float v3 = g_OUT[(size_t)(r + 3) * HC + j];
        s += v0 + v1 + v2 + v3;
        q = fmaf(v0, v0, q);
        q = fmaf(v1, v1, q);
        q = fmaf(v2, v2, q);
        q = fmaf(v3, v3, q);
    }
    for (; r < r1; r++) {
        float v = g_OUT[(size_t)r * HC + j];
        s += v;
        q = fmaf(v, v, q);
    }
    atomicAdd(&g_SUM[j], s);
    atomicAdd(&g_SSQ[j], q);
}

// ---------------------------------------------------------------------------
// z = bf16(relu(bn(out))): BN coefficients computed inline per thread
// (same math as the old k_bn_coef; SUM/SSQ/gamma/beta are L2-resident)
// ---------------------------------------------------------------------------
__global__ __launch_bounds__(256) void k_z(int N,
                                           const float* __restrict__ gamma,
                                           const float* __restrict__ beta,
                                           float invN)
{
    int i = blockIdx.x * blockDim.x + threadIdx.x;
    if (i >= N * (HC / 2)) return;
    int wd = i & (HC / 2 - 1);
    int c0 = wd * 2, c1 = c0 + 1;

    float mu0  = g_SUM[c0] * invN;
    float var0 = g_SSQ[c0] * invN - mu0 * mu0;
    float a0   = gamma[c0] * rsqrtf(var0 + 1e-5f);
    float b0   = beta[c0] - mu0 * a0;
    float mu1  = g_SUM[c1] * invN;
    float var1 = g_SSQ[c1] * invN - mu1 * mu1;
    float a1   = gamma[c1] * rsqrtf(var1 + 1e-5f);
    float b1   = beta[c1] - mu1 * a1;

    float2 v = *(const float2*)(g_OUT + (size_t)i * 2);
    float lo = fmaxf(fmaf(v.x, a0, b0), 0.f);
    float hi = fmaxf(fmaf(v.y, a1, b1), 0.f);
    g_Z[i] = pack_bf16(lo, hi);
}

// ---------------------------------------------------------------------------
// Link scoring from bf16 z: 2 label-edges per warp, uint4 gathers
// ---------------------------------------------------------------------------
__global__ __launch_bounds__(256) void k_score(const int* __restrict__ li,
                                               int EL, float* __restrict__ out)
{
    int w    = (blockIdx.x * blockDim.x + threadIdx.x) >> 5;
    int lane = threadIdx.x & 31;
    int e0 = w * 2;
    if (e0 >= EL) return;
    int ne = (e0 + 1 < EL) ? 2 : 1;

    float accv[2] = {0.f, 0.f};
#pragma unroll
    for (int q = 0; q < 2; q++) {
        if (q >= ne) break;
        int s = li[e0 + q];
        int t = li[EL + e0 + q];
        const uint4* ps = (const uint4*)(g_Z + (size_t)s * (HC / 2));
        const uint4* pt = (const uint4*)(g_Z + (size_t)t * (HC / 2));
        float acc = 0.f;
#pragma unroll
        for (int k = 0; k < 2; k++) {
            uint4 a4 = ps[lane + 32 * k];
            uint4 b4 = pt[lane + 32 * k];
            const unsigned* au = &a4.x;
            const unsigned* bu = &b4.x;
#pragma unroll
            for (int r = 0; r < 4; r++) {
                float2 af = __bfloat1622float2(*(const __nv_bfloat162*)&au[r]);
                float2 bf = __bfloat1622float2(*(const __nv_bfloat162*)&bu[r]);
                acc = fmaf(af.x, bf.x, acc);
                acc = fmaf(af.y, bf.y, acc);
            }
        }
        accv[q] = acc;
    }
#pragma unroll
    for (int q = 0; q < 2; q++) {
#pragma unroll
        for (int o = 16; o; o >>= 1)
            accv[q] += __shfl_xor_sync(0xffffffffu, accv[q], o);
    }
    if (lane == 0) {
        out[e0] = accv[0];
        if (ne == 2) out[e0 + 1] = accv[1];
    }
}

// ---------------------------------------------------------------------------
// Launch
// ---------------------------------------------------------------------------
extern "C" void kernel_launch(void* const* d_in, const int* in_sizes, int n_in,
                              void* d_out, int out_size)
{
    const float* x     = (const float*)d_in[0];
    const int*   ei    = (const int*)d_in[1];
    const int*   eli   = (const int*)d_in[2];
    const float* Wl    = (const float*)d_in[3];
    const float* Wr    = (const float*)d_in[4];
    const float* att   = (const float*)d_in[5];
    // d_in[6] = bias: cancels under BatchNorm (mean-subtracted), unused
    const float* gamma = (const float*)d_in[7];
    const float* beta  = (const float*)d_in[8];
    float* out = (float*)d_out;

    const int N  = in_sizes[0] / INCH;
    const int E  = in_sizes[1] / 2;
    const int EL = in_sizes[2] / 2;
    const int* src = ei;
    const int* dst = ei + E;
    const int nb = (N + 255) / 256;

    k_zero<<<(N + 255) / 256, 256>>>(N);

    {
        dim3 grid(8, (N + 127) / 128);
        k_gemm<<<grid, 256>>>(x, Wl, Wr, N);
    }

    k_hist<<<(E + 255) / 256, 256>>>(dst, E);
    k_scan<<<nb, 256>>>(N);
    k_scatter<<<(E + 255) / 256, 256>>>(src, dst, E);

    // one warp per node, fp32 payload, 2-edge unrolled
    k_edge<<<(N * 32 + 255) / 256, 256>>>(att, N);

    {
        int rows_per = 40;
        int blocks = (N + rows_per - 1) / rows_per;
        k_bn_stats<<<blocks, 512>>>(N, rows_per);
    }

    {
        int words = N * (HC / 2);
        k_z<<<(words + 255) / 256, 256>>>(N, gamma, beta, 1.0f / (float)N);
    }

    {
        int warps = (EL + 1) / 2;
        k_score<<<(warps * 32 + 255) / 256, 256>>>(eli, EL, out);
    }
}

// round 15
// speedup vs baseline: 1.0748x; 1.0288x over previous
#include <cuda_runtime.h>
#include <cuda_bf16.h>

// ---------------------------------------------------------------------------
// Problem constants
// ---------------------------------------------------------------------------
#define NMAX   20000
#define EMAX   320000
#define HEADS  8
#define CH     64
#define HC     512
#define INCH   512

// ---------------------------------------------------------------------------
// Scratch (static device globals; no allocations allowed)
// ---------------------------------------------------------------------------
__device__ float    g_XLR[(size_t)NMAX * 1024]; // [:,0:512]=x@Wl, [:,512:1024]=x@Wr
__device__ int      g_DEG[NMAX];
__device__ int      g_START[NMAX];
__device__ int      g_CURSOR[NMAX];
__device__ int      g_CSRC[EMAX];               // CSR source-node list
__device__ float    g_OUT[(size_t)NMAX * HC];
__device__ unsigned g_Z[(size_t)NMAX * (HC / 2)]; // bf16x2 relu(bn(out))
__device__ float    g_SUM[HC];
__device__ float    g_SSQ[HC];

// ---------------------------------------------------------------------------
// init: zero degree histogram + BN accumulators
// ---------------------------------------------------------------------------
__global__ void k_zero(int N)
{
    int i = blockIdx.x * blockDim.x + threadIdx.x;
    if (i < N) g_DEG[i] = 0;
    if (i < HC) { g_SUM[i] = 0.f; g_SSQ[i] = 0.f; }
}

// ---------------------------------------------------------------------------
// bf16 helpers
// ---------------------------------------------------------------------------
__device__ __forceinline__ unsigned pack_bf16(float lo, float hi)
{
    unsigned r;
    asm("cvt.rn.bf16x2.f32 %0, %1, %2;" : "=r"(r) : "f"(hi), "f"(lo));
    return r;
}

__device__ __forceinline__ void mma_bf16(float c[4], const unsigned a[4],
                                         const unsigned b[2])
{
    asm volatile(
        "mma.sync.aligned.m16n8k16.row.col.f32.bf16.bf16.f32 "
        "{%0,%1,%2,%3},{%4,%5,%6,%7},{%8,%9},{%0,%1,%2,%3};"
        : "+f"(c[0]), "+f"(c[1]), "+f"(c[2]), "+f"(c[3])
        : "r"(a[0]), "r"(a[1]), "r"(a[2]), "r"(a[3]),
          "r"(b[0]), "r"(b[1]));
}

// ---------------------------------------------------------------------------
// bf16 GEMM, double-buffered: g_XLR[M,1024] = x[M,512] @ [Wl | Wr]
// block tile 128x128, BK=16, 256 thr = 8 warps, warp tile 32x64.
// ---------------------------------------------------------------------------
#define KKPAD 132
__global__ __launch_bounds__(256) void k_gemm(const float* __restrict__ x,
                                              const float* __restrict__ Wl,
                                              const float* __restrict__ Wr,
                                              int M)
{
    __shared__ unsigned As2[2][8][KKPAD];
    __shared__ unsigned Bs2[2][8][KKPAD];

    const int bn   = blockIdx.x;
    const int row0 = blockIdx.y * 128;
    const float* W = (bn < 4) ? Wl : Wr;
    const int col0 = (bn & 3) * 128;

    const int tid  = threadIdx.x;
    const int warp = tid >> 5;
    const int lane = tid & 31;
    const int wm   = warp >> 1;
    const int wn   = warp & 1;
    const int gid  = lane >> 2;
    const int tig  = lane & 3;

    const int a_r = tid >> 2;
    const int a_c = (tid & 3) << 2;
    const int b_kk = tid >> 5;
    const int b_n  = (tid & 31) << 2;

    float c[2][8][4];
#pragma unroll
    for (int i = 0; i < 2; i++)
#pragma unroll
        for (int j = 0; j < 8; j++)
#pragma unroll
            for (int q = 0; q < 4; q++) c[i][j][q] = 0.f;

    float4 va[2];
    float4 vb0, vb1;

#pragma unroll
    for (int i = 0; i < 2; i++) {
        int gr = row0 + a_r + i * 64;
        va[i] = make_float4(0.f, 0.f, 0.f, 0.f);
        if (gr < M) va[i] = *(const float4*)(x + (size_t)gr * INCH + a_c);
    }
    vb0 = *(const float4*)(W + (size_t)(2 * b_kk) * HC + col0 + b_n);
    vb1 = *(const float4*)(W + (size_t)(2 * b_kk + 1) * HC + col0 + b_n);

#pragma unroll
    for (int i = 0; i < 2; i++) {
        int r = a_r + i * 64;
        As2[0][(a_c >> 1) + 0][r] = pack_bf16(va[i].x, va[i].y);
        As2[0][(a_c >> 1) + 1][r] = pack_bf16(va[i].z, va[i].w);
    }
    {
        uint4 t;
        t.x = pack_bf16(vb0.x, vb1.x);
        t.y = pack_bf16(vb0.y, vb1.y);
        t.z = pack_bf16(vb0.z, vb1.z);
        t.w = pack_bf16(vb0.w, vb1.w);
        *(uint4*)&Bs2[0][b_kk][b_n] = t;
    }
    __syncthreads();

    int buf = 0;
    for (int k0 = 0; k0 < INCH; k0 += 16) {
        const bool last = (k0 + 16 >= INCH);
        if (!last) {
#pragma unroll
            for (int i = 0; i < 2; i++) {
                int gr = row0 + a_r + i * 64;
                va[i] = make_float4(0.f, 0.f, 0.f, 0.f);
                if (gr < M)
                    va[i] = *(const float4*)(x + (size_t)gr * INCH + k0 + 16 + a_c);
            }
            vb0 = *(const float4*)(W + (size_t)(k0 + 16 + 2 * b_kk) * HC + col0 + b_n);
            vb1 = *(const float4*)(W + (size_t)(k0 + 16 + 2 * b_kk + 1) * HC + col0 + b_n);
        }

        {
            unsigned a[2][4];
#pragma unroll
            for (int mt = 0; mt < 2; mt++) {
                int mr = wm * 32 + mt * 16 + gid;
                a[mt][0] = As2[buf][tig][mr];
                a[mt][1] = As2[buf][tig][mr + 8];
                a[mt][2] = As2[buf][tig + 4][mr];
                a[mt][3] = As2[buf][tig + 4][mr + 8];
            }
            unsigned b[8][2];
#pragma unroll
            for (int nt = 0; nt < 8; nt++) {
                int nc = wn * 64 + nt * 8 + gid;
                b[nt][0] = Bs2[buf][tig][nc];
                b[nt][1] = Bs2[buf][tig + 4][nc];
            }
#pragma unroll
            for (int mt = 0; mt < 2; mt++)
#pragma unroll
                for (int nt = 0; nt < 8; nt++)
                    mma_bf16(c[mt][nt], a[mt], b[nt]);
        }

        if (!last) {
            int nb = buf ^ 1;
#pragma unroll
            for (int i = 0; i < 2; i++) {
                int r = a_r + i * 64;
                As2[nb][(a_c >> 1) + 0][r] = pack_bf16(va[i].x, va[i].y);
                As2[nb][(a_c >> 1) + 1][r] = pack_bf16(va[i].z, va[i].w);
            }
            uint4 t;
            t.x = pack_bf16(vb0.x, vb1.x);
            t.y = pack_bf16(vb0.y, vb1.y);
            t.z = pack_bf16(vb0.z, vb1.z);
            t.w = pack_bf16(vb0.w, vb1.w);
            *(uint4*)&Bs2[nb][b_kk][b_n] = t;
            __syncthreads();
            buf = nb;
        }
    }

#pragma unroll
    for (int mt = 0; mt < 2; mt++) {
#pragma unroll
        for (int nt = 0; nt < 8; nt++) {
            int r   = row0 + wm * 32 + mt * 16 + gid;
            int col = bn * 128 + wn * 64 + nt * 8 + 2 * tig;
            if (r < M)
                *(float2*)(g_XLR + (size_t)r * 1024 + col) =
                    make_float2(c[mt][nt][0], c[mt][nt][1]);
            if (r + 8 < M)
                *(float2*)(g_XLR + (size_t)(r + 8) * 1024 + col) =
                    make_float2(c[mt][nt][2], c[mt][nt][3]);
        }
    }
}

// ---------------------------------------------------------------------------
// CSR build: histogram -> single-kernel scan -> scatter
// ---------------------------------------------------------------------------
__global__ void k_hist(const int* __restrict__ dst, int E)
{
    int e = blockIdx.x * blockDim.x + threadIdx.x;
    if (e < E) atomicAdd(&g_DEG[dst[e]], 1);
}

__global__ __launch_bounds__(256) void k_scan(int N)
{
    __shared__ int wsum[8];
    __shared__ int wscan[8];
    __shared__ int sh_base;
    const int b = blockIdx.x;
    const int t = threadIdx.x;
    const int lane = t & 31, wid = t >> 5;

    int ps = 0;
    int lim = b * 256;
    for (int i = t; i < lim; i += 256) ps += g_DEG[i];
#pragma unroll
    for (int o = 16; o; o >>= 1) ps += __shfl_xor_sync(0xffffffffu, ps, o);
    if (lane == 0) wsum[wid] = ps;
    __syncthreads();
    if (t == 0) {
        int s = 0;
#pragma unroll
        for (int w2 = 0; w2 < 8; w2++) s += wsum[w2];
        sh_base = s;
    }
    __syncthreads();
    const int base = sh_base;

    int i = b * 256 + t;
    int v = (i < N) ? g_DEG[i] : 0;
    int xinc = v;
#pragma unroll
    for (int o = 1; o < 32; o <<= 1) {
        int y = __shfl_up_sync(0xffffffffu, xinc, o);
        if (lane >= o) xinc += y;
    }
    if (lane == 31) wscan[wid] = xinc;
    __syncthreads();
    int off = 0;
#pragma unroll
    for (int w2 = 0; w2 < 8; w2++) off += (w2 < wid) ? wscan[w2] : 0;
    if (i < N) {
        int e = base + off + xinc - v;
        g_START[i]  = e;
        g_CURSOR[i] = e;
    }
}

__global__ void k_scatter(const int* __restrict__ src,
                          const int* __restrict__ dst, int E)
{
    int e = blockIdx.x * blockDim.x + threadIdx.x;
    if (e >= E) return;
    int d   = dst[e];
    int pos = atomicAdd(&g_CURSOR[d], 1);
    g_CSRC[pos] = src[e];
}

// ---------------------------------------------------------------------------
// Fused GATv2 with ONLINE softmax, 2 edges per iteration (empirical optimum).
// One warp per destination node. Lane owns channels c = lane*4 + 128*k.
// ---------------------------------------------------------------------------
__global__ __launch_bounds__(256) void k_edge(const float* __restrict__ att, int N)
{
    int w    = (blockIdx.x * blockDim.x + threadIdx.x) >> 5;
    int lane = threadIdx.x & 31;
    if (w >= N) return;
    const int d     = w;
    const int start = g_START[d];
    const int deg   = g_DEG[d];
    const int c0    = lane * 4;

    float4 attv[4], xrv[4];
#pragma unroll
    for (int k = 0; k < 4; k++) {
        attv[k] = __ldg((const float4*)(att + c0 + 128 * k));
        xrv[k]  = *(const float4*)(g_XLR + (size_t)d * 1024 + 512 + c0 + 128 * k);
    }

    float  m[4], dnm[4];
    float4 acc[4];
#pragma unroll
    for (int k = 0; k < 4; k++) {
        m[k] = -1e30f; dnm[k] = 0.f;
        acc[k] = make_float4(0.f, 0.f, 0.f, 0.f);
    }

    int j = 0;
    for (; j + 2 <= deg; j += 2) {
        int s0 = g_CSRC[start + j];
        int s1 = g_CSRC[start + j + 1];
        const float* xl0 = g_XLR + (size_t)s0 * 1024;
        const float* xl1 = g_XLR + (size_t)s1 * 1024;
        float4 v[2][4];
        float  p[2][4];
#pragma unroll
        for (int k = 0; k < 4; k++) v[0][k] = *(const float4*)(xl0 + c0 + 128 * k);
#pragma unroll
        for (int k = 0; k < 4; k++) v[1][k] = *(const float4*)(xl1 + c0 + 128 * k);

#pragma unroll
        for (int e2 = 0; e2 < 2; e2++) {
#pragma unroll
            for (int k = 0; k < 4; k++) {
                float tx = v[e2][k].x + xrv[k].x, ty = v[e2][k].y + xrv[k].y;
                float tz = v[e2][k].z + xrv[k].z, tw = v[e2][k].w + xrv[k].w;
                tx = (tx > 0.f) ? tx : 0.2f * tx;
                ty = (ty > 0.f) ? ty : 0.2f * ty;
                tz = (tz > 0.f) ? tz : 0.2f * tz;
                tw = (tw > 0.f) ? tw : 0.2f * tw;
                p[e2][k] = tx * attv[k].x + ty * attv[k].y +
                           tz * attv[k].z + tw * attv[k].w;
            }
        }
#pragma unroll
        for (int e2 = 0; e2 < 2; e2++)
#pragma unroll
            for (int k = 0; k < 4; k++) {
                p[e2][k] += __shfl_xor_sync(0xffffffffu, p[e2][k], 1);
                p[e2][k] += __shfl_xor_sync(0xffffffffu, p[e2][k], 2);
                p[e2][k] += __shfl_xor_sync(0xffffffffu, p[e2][k], 4);
                p[e2][k] += __shfl_xor_sync(0xffffffffu, p[e2][k], 8);
            }
#pragma unroll
        for (int e2 = 0; e2 < 2; e2++) {
#pragma unroll
            for (int k = 0; k < 4; k++) {
                float mn = fmaxf(m[k], p[e2][k]);
                float r  = __expf(m[k] - mn);
                float e  = __expf(p[e2][k] - mn);
                dnm[k]   = fmaf(dnm[k], r, e);
                acc[k].x = fmaf(acc[k].x, r, e * v[e2][k].x);
                acc[k].y = fmaf(acc[k].y, r, e * v[e2][k].y);
                acc[k].z = fmaf(acc[k].z, r, e * v[e2][k].z);
                acc[k].w = fmaf(acc[k].w, r, e * v[e2][k].w);
                m[k] = mn;
            }
        }
    }
    if (j < deg) {
        int s = g_CSRC[start + j];
        const float* xl = g_XLR + (size_t)s * 1024;
        float4 v[4];
        float  p[4];
#pragma unroll
        for (int k = 0; k < 4; k++) {
            v[k] = *(const float4*)(xl + c0 + 128 * k);
            float tx = v[k].x + xrv[k].x, ty = v[k].y + xrv[k].y;
            float tz = v[k].z + xrv[k].z, tw = v[k].w + xrv[k].w;
            tx = (tx > 0.f) ? tx : 0.2f * tx;
            ty = (ty > 0.f) ? ty : 0.2f * ty;
            tz = (tz > 0.f) ? tz : 0.2f * tz;
            tw = (tw > 0.f) ? tw : 0.2f * tw;
            p[k] = tx * attv[k].x + ty * attv[k].y + tz * attv[k].z + tw * attv[k].w;
        }
#pragma unroll
        for (int k = 0; k < 4; k++) {
            p[k] += __shfl_xor_sync(0xffffffffu, p[k], 1);
            p[k] += __shfl_xor_sync(0xffffffffu, p[k], 2);
            p[k] += __shfl_xor_sync(0xffffffffu, p[k], 4);
            p[k] += __shfl_xor_sync(0xffffffffu, p[k], 8);
        }
#pragma unroll
        for (int k = 0; k < 4; k++) {
            float mn = fmaxf(m[k], p[k]);
            float r  = __expf(m[k] - mn);
            float e  = __expf(p[k] - mn);
            dnm[k]   = fmaf(dnm[k], r, e);
            acc[k].x = fmaf(acc[k].x, r, e * v[k].x);
            acc[k].y = fmaf(acc[k].y, r, e * v[k].y);
            acc[k].z = fmaf(acc[k].z, r, e * v[k].z);
            acc[k].w = fmaf(acc[k].w, r, e * v[k].w);
            m[k] = mn;
        }
    }

#pragma unroll
    for (int k = 0; k < 4; k++) {
        float inv = 1.0f / (dnm[k] + 1e-16f);
        float4 o = make_float4(acc[k].x * inv, acc[k].y * inv,
                               acc[k].z * inv, acc[k].w * inv);
        *(float4*)(g_OUT + (size_t)d * HC + c0 + 128 * k) = o;
    }
}

// ---------------------------------------------------------------------------
// BatchNorm stats (4-row unroll)
// ---------------------------------------------------------------------------
__global__ __launch_bounds__(512) void k_bn_stats(int n_nodes, int rows_per)
{
    int j  = threadIdx.x;
    int r0 = blockIdx.x * rows_per;
    int r1 = min(r0 + rows_per, n_nodes);
    float s = 0.f, q = 0.f;
    int r = r0;
    for (; r + 4 <= r1; r += 4) {
        float v0 = g_OUT[(size_t)(r + 0) * HC + j];
        float v1 = g_OUT[(size_t)(r + 1) * HC + j];
        float v2 = g_OUT[(size_t)(r + 2) * HC + j];
        float v3 = g_OUT[(size_t)(r + 3) * HC + j];
        s += v0 + v1 + v2 + v3;
        q = fmaf(v0, v0, q);
        q = fmaf(v1, v1, q);
        q = fmaf(v2, v2, q);
        q = fmaf(v3, v3, q);
    }
    for (; r < r1; r++) {
        float v = g_OUT[(size_t)r * HC + j];
        s += v;
        q = fmaf(v, v, q);
    }
    atomicAdd(&g_SUM[j], s);
    atomicAdd(&g_SSQ[j], q);
}

// ---------------------------------------------------------------------------
// z = bf16(relu(bn(out))): BN coefficients computed inline per thread
// ---------------------------------------------------------------------------
__global__ __launch_bounds__(256) void k_z(int N,
                                           const float* __restrict__ gamma,
                                           const float* __restrict__ beta,
                                           float invN)
{
    int i = blockIdx.x * blockDim.x + threadIdx.x;
    if (i >= N * (HC / 2)) return;
    int wd = i & (HC / 2 - 1);
    int c0 = wd * 2, c1 = c0 + 1;

    float mu0  = g_SUM[c0] * invN;
    float var0 = g_SSQ[c0] * invN - mu0 * mu0;
    float a0   = gamma[c0] * rsqrtf(var0 + 1e-5f);
    float b0   = beta[c0] - mu0 * a0;
    float mu1  = g_SUM[c1] * invN;
    float var1 = g_SSQ[c1] * invN - mu1 * mu1;
    float a1   = gamma[c1] * rsqrtf(var1 + 1e-5f);
    float b1   = beta[c1] - mu1 * a1;

    float2 v = *(const float2*)(g_OUT + (size_t)i * 2);
    float lo = fmaxf(fmaf(v.x, a0, b0), 0.f);
    float hi = fmaxf(fmaf(v.y, a1, b1), 0.f);
    g_Z[i] = pack_bf16(lo, hi);
}

// ---------------------------------------------------------------------------
// Link scoring from bf16 z: 2 label-edges per warp, uint4 gathers
// ---------------------------------------------------------------------------
__global__ __launch_bounds__(256) void k_score(const int* __restrict__ li,
                                               int EL, float* __restrict__ out)
{
    int w    = (blockIdx.x * blockDim.x + threadIdx.x) >> 5;
    int lane = threadIdx.x & 31;
    int e0 = w * 2;
    if (e0 >= EL) return;
    int ne = (e0 + 1 < EL) ? 2 : 1;

    float accv[2] = {0.f, 0.f};
#pragma unroll
    for (int q = 0; q < 2; q++) {
        if (q >= ne) break;
        int s = li[e0 + q];
        int t = li[EL + e0 + q];
        const uint4* ps = (const uint4*)(g_Z + (size_t)s * (HC / 2));
        const uint4* pt = (const uint4*)(g_Z + (size_t)t * (HC / 2));
        float acc = 0.f;
#pragma unroll
        for (int k = 0; k < 2; k++) {
            uint4 a4 = ps[lane + 32 * k];
            uint4 b4 = pt[lane + 32 * k];
            const unsigned* au = &a4.x;
            const unsigned* bu = &b4.x;
#pragma unroll
            for (int r = 0; r < 4; r++) {
                float2 af = __bfloat1622float2(*(const __nv_bfloat162*)&au[r]);
                float2 bf = __bfloat1622float2(*(const __nv_bfloat162*)&bu[r]);
                acc = fmaf(af.x, bf.x, acc);
                acc = fmaf(af.y, bf.y, acc);
            }
        }
        accv[q] = acc;
    }
#pragma unroll
    for (int q = 0; q < 2; q++) {
#pragma unroll
        for (int o = 16; o; o >>= 1)
            accv[q] += __shfl_xor_sync(0xffffffffu, accv[q], o);
    }
    if (lane == 0) {
        out[e0] = accv[0];
        if (ne == 2) out[e0 + 1] = accv[1];
    }
}

// ---------------------------------------------------------------------------
// Launch: fork CSR build onto a side stream, concurrent with the GEMM.
//   default: ev0 -> gemm ----------------------\
//   s1:      ev0 -> zero,hist,scan,scatter -> ev1 -> (default waits) -> edge...
// Event fork/join is the sanctioned multi-stream graph-capture pattern;
// stream/event creation is not a captured op and allocates no device memory.
// ---------------------------------------------------------------------------
extern "C" void kernel_launch(void* const* d_in, const int* in_sizes, int n_in,
                              void* d_out, int out_size)
{
    const float* x     = (const float*)d_in[0];
    const int*   ei    = (const int*)d_in[1];
    const int*   eli   = (const int*)d_in[2];
    const float* Wl    = (const float*)d_in[3];
    const float* Wr    = (const float*)d_in[4];
    const float* att   = (const float*)d_in[5];
    // d_in[6] = bias: cancels under BatchNorm (mean-subtracted), unused
    const float* gamma = (const float*)d_in[7];
    const float* beta  = (const float*)d_in[8];
    float* out = (float*)d_out;

    const int N  = in_sizes[0] / INCH;
    const int E  = in_sizes[1] / 2;
    const int EL = in_sizes[2] / 2;
    const int* src = ei;
    const int* dst = ei + E;
    const int nb = (N + 255) / 256;

    cudaStream_t s1;
    cudaEvent_t ev0, ev1;
    cudaStreamCreateWithFlags(&s1, cudaStreamNonBlocking);
    cudaEventCreateWithFlags(&ev0, cudaEventDisableTiming);
    cudaEventCreateWithFlags(&ev1, cudaEventDisableTiming);

    // fork
    cudaEventRecord(ev0, 0);
    cudaStreamWaitEvent(s1, ev0, 0);

    // side stream: CSR build chain
    k_zero<<<(N + 255) / 256, 256, 0, s1>>>(N);
    k_hist<<<(E + 255) / 256, 256, 0, s1>>>(dst, E);
    k_scan<<<nb, 256, 0, s1>>>(N);
    k_scatter<<<(E + 255) / 256, 256, 0, s1>>>(src, dst, E);
    cudaEventRecord(ev1, s1);

    // default stream: GEMM (independent of CSR build)
    {
        dim3 grid(8, (N + 127) / 128);
        k_gemm<<<grid, 256>>>(x, Wl, Wr, N);
    }

    // join: k_edge needs both XLR (gemm) and CSR
    cudaStreamWaitEvent(0, ev1, 0);

    k_edge<<<(N * 32 + 255) / 256, 256>>>(att, N);

    {
        int rows_per = 40;
        int blocks = (N + rows_per - 1) / rows_per;
        k_bn_stats<<<blocks, 512>>>(N, rows_per);
    }

    {
        int words = N * (HC / 2);
        k_z<<<(words + 255) / 256, 256>>>(N, gamma, beta, 1.0f / (float)N);
    }

    {
        int warps = (EL + 1) / 2;
        k_score<<<(warps * 32 + 255) / 256, 256>>>(eli, EL, out);
    }
}